// round 9
// baseline (speedup 1.0000x reference)
#include <cuda_runtime.h>
#include <cstdint>

typedef unsigned long long ull;

#define BATCH   2048
#define TSTEPS  250
#define DIN     128
#define HID     100
#define G4      400
#define MTOT    (BATCH*TSTEPS)

// Scratch for xz : GATE-INTERLEAVED layout [m][j][g]  (index = m*400 + j*4 + g)
__device__ float g_xz[(size_t)MTOT * G4];

// ---------------------------------------------------------------------------
// helpers
// ---------------------------------------------------------------------------
__device__ __forceinline__ uint32_t sptr(const void* p) {
    return (uint32_t)__cvta_generic_to_shared(p);
}
__device__ __forceinline__ void lds2(ull& a, ull& b, uint32_t addr) {
    asm volatile("ld.shared.v2.b64 {%0,%1}, [%2];" : "=l"(a), "=l"(b) : "r"(addr));
}
__device__ __forceinline__ ull lds1(uint32_t addr) {
    ull a; asm volatile("ld.shared.b64 %0, [%1];" : "=l"(a) : "r"(addr)); return a;
}
__device__ __forceinline__ void ffma2(ull& d, ull a, ull b) {
    asm volatile("fma.rn.f32x2 %0, %1, %2, %0;" : "+l"(d) : "l"(a), "l"(b));
}
__device__ __forceinline__ ull pack2(float lo, float hi) {
    ull r; asm("mov.b64 %0, {%1,%2};" : "=l"(r) : "f"(lo), "f"(hi)); return r;
}
__device__ __forceinline__ float hsum2(ull v) {
    float lo, hi; asm("mov.b64 {%0,%1}, %2;" : "=f"(lo), "=f"(hi) : "l"(v));
    return lo + hi;
}
__device__ __forceinline__ void cpasync16(uint32_t dst, const void* src) {
    asm volatile("cp.async.ca.shared.global [%0], [%1], 16;" :: "r"(dst), "l"(src));
}
__device__ __forceinline__ uint32_t t32(float f) {
    uint32_t u; asm("cvt.rna.tf32.f32 %0, %1;" : "=r"(u) : "f"(f)); return u;
}
__device__ __forceinline__ void mma_tf32(float c[4], uint32_t a0, uint32_t a1,
                                         uint32_t a2, uint32_t a3,
                                         uint32_t b0, uint32_t b1) {
    asm volatile(
        "mma.sync.aligned.m16n8k8.row.col.f32.tf32.tf32.f32 "
        "{%0,%1,%2,%3}, {%4,%5,%6,%7}, {%8,%9}, {%0,%1,%2,%3};"
        : "+f"(c[0]), "+f"(c[1]), "+f"(c[2]), "+f"(c[3])
        : "r"(a0), "r"(a1), "r"(a2), "r"(a3), "r"(b0), "r"(b1));
}

// ---------------------------------------------------------------------------
// Kernel 1: xz = x@Wi + bh via 3xTF32 split mma.sync (near-fp32 precision):
//   a = ah + al, b = bh + bl (cvt.rna.tf32);  acc += ah*bh + ah*bl + al*bh
// M=512000, K=128, N=400. CTA: 128 thr (4 warps), BM=64, BN=80 where the 80
// columns are {g*100 + j0 + jj : g in 0..3, jj in 0..19}  (j0 = 20*blockIdx.y).
// Epilogue stages through smem and writes coalesced float4 in [m][j][g] order.
// ---------------------------------------------------------------------------
#define BM 64
#define XS_STR 132    // x tile row stride (floats): conflict-free a-frag loads
#define WS_STR 88     // Wi tile row stride (floats): conflict-free b-frag loads
#define SO_STR 84     // staging row stride

__global__ __launch_bounds__(128) void gemm_xz_kernel(
    const float* __restrict__ x,
    const float* __restrict__ Wi,
    const float* __restrict__ bh)
{
    extern __shared__ float sm1[];
    float* xs  = sm1;                         // [64][132]
    float* ws  = sm1 + 64 * XS_STR;           // [128][88] (k-major; 80 cols used)
    float* sbh = ws + 128 * WS_STR;           // [80] bias in output-staging order
    float* sout = ws;                         // reuse ws region for epilogue stage

    const int tid = threadIdx.x;
    const int m0  = blockIdx.x * BM;
    const int j0  = blockIdx.y * 20;

    // bias in staged order: p = jj*4 + gg  ->  bh[gg*100 + j0 + jj]
    if (tid < 80) sbh[tid] = bh[(tid & 3) * 100 + j0 + (tid >> 2)];

    // x tile: 64 rows x 32 16B-chunks
    {
        const uint32_t xb = sptr(xs);
#pragma unroll
        for (int q = 0; q < 16; q++) {
            int i = tid + q * 128;
            int r = i >> 5, c = i & 31;
            cpasync16(xb + (r * XS_STR + c * 4) * 4,
                      x + (size_t)(m0 + r) * DIN + c * 4);
        }
    }
    // Wi tile: 128 k-rows x 4 gates x 5 16B-chunks; local col = gg*20 + jj
    {
        const uint32_t wb = sptr(ws);
#pragma unroll
        for (int q = 0; q < 20; q++) {
            int i = tid + q * 128;
            int k = i / 20, rem = i % 20;
            int gg = rem / 5, cc = rem % 5;
            cpasync16(wb + (k * WS_STR + gg * 20 + cc * 4) * 4,
                      Wi + (size_t)k * G4 + gg * 100 + j0 + cc * 4);
        }
    }
    asm volatile("cp.async.commit_group;");
    asm volatile("cp.async.wait_group 0;");
    __syncthreads();

    const int warp = tid >> 5, lane = tid & 31;
    const int gid = lane >> 2, tig = lane & 3;
    const int r0w = warp * 16;

    float acc[10][4];
#pragma unroll
    for (int nt = 0; nt < 10; nt++)
#pragma unroll
        for (int q = 0; q < 4; q++) acc[nt][q] = 0.f;

    const float* xa0 = xs + (r0w + gid) * XS_STR;
    const float* xa1 = xs + (r0w + gid + 8) * XS_STR;

#pragma unroll
    for (int kk = 0; kk < 16; kk++) {
        const int k0 = kk * 8;
        float af[4];
        af[0] = xa0[k0 + tig];
        af[1] = xa1[k0 + tig];
        af[2] = xa0[k0 + tig + 4];
        af[3] = xa1[k0 + tig + 4];
        uint32_t ah[4], al[4];
#pragma unroll
        for (int q = 0; q < 4; q++) {
            ah[q] = t32(af[q]);
            al[q] = t32(af[q] - __uint_as_float(ah[q]));
        }
        const float* w0 = ws + (k0 + tig) * WS_STR + gid;
        const float* w1 = ws + (k0 + tig + 4) * WS_STR + gid;
#pragma unroll
        for (int nt = 0; nt < 10; nt++) {
            float b0f = w0[nt * 8];
            float b1f = w1[nt * 8];
            uint32_t bh0 = t32(b0f);
            uint32_t bh1 = t32(b1f);
            uint32_t bl0 = t32(b0f - __uint_as_float(bh0));
            uint32_t bl1 = t32(b1f - __uint_as_float(bh1));
            mma_tf32(acc[nt], ah[0], ah[1], ah[2], ah[3], bh0, bh1);
            mma_tf32(acc[nt], ah[0], ah[1], ah[2], ah[3], bl0, bl1);
            mma_tf32(acc[nt], al[0], al[1], al[2], al[3], bh0, bh1);
        }
    }
    __syncthreads();   // done reading ws; reuse as staging

    // stage accums into sout[row][p], p = (n'%20)*4 + n'/20
#pragma unroll
    for (int nt = 0; nt < 10; nt++) {
        int n0c = nt * 8 + 2 * tig;
        int n1c = n0c + 1;
        int p0 = (n0c % 20) * 4 + n0c / 20;
        int p1 = (n1c % 20) * 4 + n1c / 20;
        sout[(r0w + gid) * SO_STR + p0]     = acc[nt][0];
        sout[(r0w + gid) * SO_STR + p1]     = acc[nt][1];
        sout[(r0w + gid + 8) * SO_STR + p0] = acc[nt][2];
        sout[(r0w + gid + 8) * SO_STR + p1] = acc[nt][3];
    }
    __syncthreads();

    // coalesced write-out: 64 rows x 20 float4 (+bias)
    float4* gout = (float4*)g_xz;
#pragma unroll
    for (int q = 0; q < 10; q++) {
        int i = tid + q * 128;
        int r = i / 20, c = i % 20;
        float4 v;
        v.x = sout[r * SO_STR + 4 * c + 0] + sbh[4 * c + 0];
        v.y = sout[r * SO_STR + 4 * c + 1] + sbh[4 * c + 1];
        v.z = sout[r * SO_STR + 4 * c + 2] + sbh[4 * c + 2];
        v.w = sout[r * SO_STR + 4 * c + 3] + sbh[4 * c + 3];
        gout[(size_t)(m0 + r) * 100 + 20 * blockIdx.y + c] = v;
    }
}

// ---------------------------------------------------------------------------
// Kernel 2: persistent LSTM recurrence + FUSED projection, f32x2.
// 128 CTAs x 16 rows, 200 threads: thread = (j = tid%100, rr = tid/100),
// owns 8 rows. Double-buffered h -> ONE barrier per step.
//
// Fusion: projection(t-1) and recurrence(t) read the SAME h buffer, so both
// run in ONE k-loop per step: each h value loaded once feeds 8 recurrence
// FFMA2 + 2 projection FFMA2. out[t-1] stored in iteration t (skipped at t=0);
// the final projection (t=249) runs in an epilogue loop.
// ---------------------------------------------------------------------------
__device__ __forceinline__ float sigf(float xv) {
    return __fdividef(1.f, 1.f + __expf(-xv));
}
__device__ __forceinline__ float tanh_f(float xv) {
    float e = __expf(2.f * xv);
    return 1.f - __fdividef(2.f, e + 1.f);
}

__global__ __launch_bounds__(200) void lstm_kernel(
    const float* __restrict__ Wh,
    const float* __restrict__ Wd,
    const float* __restrict__ bd,
    float* __restrict__ out)
{
    extern __shared__ float sm2[];
    float* Wq  = sm2;                 // 40000 floats
    float* Wdp = sm2 + 40000;         // 10000 floats
    float* hsm = sm2 + 50000;         // 2 x 1600 floats (double buffer)
    float* bds = sm2 + 53200;         // 100 floats

    const int tid = threadIdx.x;      // 0..199

    for (int i = tid; i < HID * G4; i += 200) {
        int k = i / G4, c = i - k * G4;
        int k2 = k >> 1, kl = k & 1;
        int g = c / HID, j = c - g * HID;
        int gp = g >> 1, gl = g & 1;
        Wq[(((k2 * 2 + gp) * HID + j) << 2) + gl * 2 + kl] = Wh[i];
    }
    for (int i = tid; i < HID * HID; i += 200) {
        int k = i / HID, j = i - k * HID;
        Wdp[(k >> 1) * (2 * HID) + j * 2 + (k & 1)] = Wd[i];
    }
    for (int i = tid; i < 16 * HID; i += 200) hsm[i] = 0.f;   // buffer 0 only
    if (tid < HID) bds[tid] = bd[tid];
    __syncthreads();

    const int j  = tid % HID;
    const int rr = tid / HID;                     // 0..1
    const int r0 = blockIdx.x * 16 + rr * 8;      // first of this thread's 8 rows

    const uint32_t hbase = sptr(hsm) + (rr * 8) * (HID * 4);
    const uint32_t wqb   = sptr(Wq)  + j * 16;
    const uint32_t wdb   = sptr(Wdp) + j * 8;
    const float bj = bds[j];

    float cst[8];
#pragma unroll
    for (int i = 0; i < 8; i++) cst[i] = 0.f;

    // prefetched xz (current step): 8 rows x float4(4 gates)
    const float4* xzg = (const float4*)g_xz;
    float4 xzn[8];
#pragma unroll
    for (int i = 0; i < 8; i++)
        xzn[i] = __ldcs(xzg + ((size_t)(r0 + i) * TSTEPS) * HID + j);

    int cur = 0;
    for (int t = 0; t < TSTEPS; t++) {
        ull acc[8][4];
#pragma unroll
        for (int i = 0; i < 8; i++) {
            acc[i][0] = pack2(xzn[i].x, 0.f);
            acc[i][1] = pack2(xzn[i].y, 0.f);
            acc[i][2] = pack2(xzn[i].z, 0.f);
            acc[i][3] = pack2(xzn[i].w, 0.f);
        }
        if (t + 1 < TSTEPS) {
#pragma unroll
            for (int i = 0; i < 8; i++)
                xzn[i] = __ldcs(xzg + ((size_t)(r0 + i) * TSTEPS + (t + 1)) * HID + j);
        }

        ull pv[8];
#pragma unroll
        for (int i = 0; i < 8; i++) pv[i] = 0ull;

        const uint32_t hrow = hbase + cur * 6400;

        // FUSED loop: recurrence(t) + projection(t-1), one pass over h
#pragma unroll 5
        for (int k4 = 0; k4 < 25; k4++) {
            ull a[8][2];
#pragma unroll
            for (int i = 0; i < 8; i++)
                lds2(a[i][0], a[i][1], hrow + i * (HID * 4) + k4 * 16);
            ull bg[2][4];
#pragma unroll
            for (int kl = 0; kl < 2; kl++) {
                int k2 = 2 * k4 + kl;
                lds2(bg[kl][0], bg[kl][1], wqb + (k2 * 2 + 0) * (HID * 16));
                lds2(bg[kl][2], bg[kl][3], wqb + (k2 * 2 + 1) * (HID * 16));
            }
            const ull w0 = lds1(wdb + (2 * k4 + 0) * (HID * 8));
            const ull w1 = lds1(wdb + (2 * k4 + 1) * (HID * 8));
#pragma unroll
            for (int i = 0; i < 8; i++) {
#pragma unroll
                for (int g = 0; g < 4; g++) {
                    ffma2(acc[i][g], a[i][0], bg[0][g]);
                    ffma2(acc[i][g], a[i][1], bg[1][g]);
                }
                ffma2(pv[i], a[i][0], w0);
                ffma2(pv[i], a[i][1], w1);
            }
        }

        // store projection of step t-1 (h state read above is post-step-(t-1))
        if (t > 0) {
#pragma unroll
            for (int i = 0; i < 8; i++) {
                const float v = hsum2(pv[i]) + bj;
                out[((size_t)(r0 + i) * TSTEPS + (t - 1)) * HID + j] =
                    fmaxf(v, 0.f);
            }
        }

        // gates (i, f, g, o)
        float hnew[8];
#pragma unroll
        for (int i = 0; i < 8; i++) {
            const float ig = sigf(hsum2(acc[i][0]));
            const float fg = sigf(hsum2(acc[i][1]));
            const float gg = tanh_f(hsum2(acc[i][2]));
            const float og = sigf(hsum2(acc[i][3]));
            const float c  = fg * cst[i] + ig * gg;
            cst[i]  = c;
            hnew[i] = og * tanh_f(c);
        }

        // write new h into the OTHER buffer; single barrier
        float* hn = hsm + (cur ^ 1) * 1600;
#pragma unroll
        for (int i = 0; i < 8; i++) hn[(rr * 8 + i) * HID + j] = hnew[i];
        __syncthreads();

        cur ^= 1;
    }

    // epilogue: projection of the final step (t = 249)
    {
        ull pv[8];
#pragma unroll
        for (int i = 0; i < 8; i++) pv[i] = 0ull;
        const uint32_t hrow = hbase + cur * 6400;
#pragma unroll 5
        for (int k4 = 0; k4 < 25; k4++) {
            ull a[8][2];
#pragma unroll
            for (int i = 0; i < 8; i++)
                lds2(a[i][0], a[i][1], hrow + i * (HID * 4) + k4 * 16);
            const ull w0 = lds1(wdb + (2 * k4 + 0) * (HID * 8));
            const ull w1 = lds1(wdb + (2 * k4 + 1) * (HID * 8));
#pragma unroll
            for (int i = 0; i < 8; i++) {
                ffma2(pv[i], a[i][0], w0);
                ffma2(pv[i], a[i][1], w1);
            }
        }
#pragma unroll
        for (int i = 0; i < 8; i++) {
            const float v = hsum2(pv[i]) + bj;
            out[((size_t)(r0 + i) * TSTEPS + (TSTEPS - 1)) * HID + j] =
                fmaxf(v, 0.f);
        }
    }
}

// ---------------------------------------------------------------------------
// Launch
// ---------------------------------------------------------------------------
extern "C" void kernel_launch(void* const* d_in, const int* in_sizes, int n_in,
                              void* d_out, int out_size)
{
    const float* x  = (const float*)d_in[0];   // [2048,250,128]
    const float* Wi = (const float*)d_in[1];   // [128,400]
    const float* Wh = (const float*)d_in[2];   // [100,400]
    const float* bh = (const float*)d_in[3];   // [400]
    const float* Wd = (const float*)d_in[4];   // [100,100]
    const float* bd = (const float*)d_in[5];   // [100]
    float* out = (float*)d_out;                // [2048,250,100]

    const int smem1 = (64 * XS_STR + 128 * WS_STR + 80) * 4;   // 79,168 B
    const int smem2 = 53300 * 4;                               // 213,200 B
    cudaFuncSetAttribute(gemm_xz_kernel,
                         cudaFuncAttributeMaxDynamicSharedMemorySize, smem1);
    cudaFuncSetAttribute(lstm_kernel,
                         cudaFuncAttributeMaxDynamicSharedMemorySize, smem2);

    dim3 g1(MTOT / BM, 5);   // 8000 x 5
    gemm_xz_kernel<<<g1, 128, smem1>>>(x, Wi, bh);
    lstm_kernel<<<BATCH / 16, 200, smem2>>>(Wh, Wd, bd, out);
}

// round 10
// speedup vs baseline: 1.0984x; 1.0984x over previous
#include <cuda_runtime.h>
#include <cuda_fp16.h>
#include <cstdint>

typedef unsigned long long ull;

#define BATCH   2048
#define TSTEPS  250
#define DIN     128
#define HID     100
#define G4      400
#define MTOT    (BATCH*TSTEPS)

// Scratch for xz : GATE-INTERLEAVED layout [m][j][g]  (index = m*400 + j*4 + g)
__device__ float g_xz[(size_t)MTOT * G4];

// ---------------------------------------------------------------------------
// helpers
// ---------------------------------------------------------------------------
__device__ __forceinline__ uint32_t sptr(const void* p) {
    return (uint32_t)__cvta_generic_to_shared(p);
}
__device__ __forceinline__ void lds2(ull& a, ull& b, uint32_t addr) {
    asm volatile("ld.shared.v2.b64 {%0,%1}, [%2];" : "=l"(a), "=l"(b) : "r"(addr));
}
__device__ __forceinline__ ull lds1(uint32_t addr) {
    ull a; asm volatile("ld.shared.b64 %0, [%1];" : "=l"(a) : "r"(addr)); return a;
}
__device__ __forceinline__ void ffma2(ull& d, ull a, ull b) {
    asm volatile("fma.rn.f32x2 %0, %1, %2, %0;" : "+l"(d) : "l"(a), "l"(b));
}
__device__ __forceinline__ ull pack2(float lo, float hi) {
    ull r; asm("mov.b64 %0, {%1,%2};" : "=l"(r) : "f"(lo), "f"(hi)); return r;
}
__device__ __forceinline__ float hsum2(ull v) {
    float lo, hi; asm("mov.b64 {%0,%1}, %2;" : "=f"(lo), "=f"(hi) : "l"(v));
    return lo + hi;
}
__device__ __forceinline__ void mma_f16(float c[4], uint32_t a0, uint32_t a1,
                                        uint32_t a2, uint32_t a3,
                                        uint32_t b0, uint32_t b1) {
    asm volatile(
        "mma.sync.aligned.m16n8k16.row.col.f32.f16.f16.f32 "
        "{%0,%1,%2,%3}, {%4,%5,%6,%7}, {%8,%9}, {%0,%1,%2,%3};"
        : "+f"(c[0]), "+f"(c[1]), "+f"(c[2]), "+f"(c[3])
        : "r"(a0), "r"(a1), "r"(a2), "r"(a3), "r"(b0), "r"(b1));
}

// ---------------------------------------------------------------------------
// Kernel 1: xz = x@Wi + bh via fp16 split-3 mma.sync (near-fp32 precision):
//   a = ah + al/2048, b = bh + bl/2048   (hi = f16(v), lo = f16((v-hi)*2048))
//   accH += ah*bh;   accL += ah*bl + al*bh;   result = accH + accL/2048
// Lo terms are pre-scaled by 2^11 so they stay in f16 normal range.
// M=512000, K=128 (64 k-pairs), N=400. CTA: 128 thr (4 warps), BM=64, BN=80
// with local col n' = gg*20+jj <-> global col gg*100 + j0 + jj (j0=20*by).
// Tiles pre-split into f16x2 hi/lo smem once; main loop is pure LDS + MMA.
// Epilogue stages through smem, writes coalesced float4 in [m][j][g] order.
// ---------------------------------------------------------------------------
#define BM 64
#define A_STR 68     // kpair stride for A tiles: bank = 4*gid+tig, conflict-free
#define B_STR 104    // n stride for B tiles: 104%32=8 -> bank = 8*tig+gid, CF
#define SO_STR 84    // staging row stride

__global__ __launch_bounds__(128) void gemm_xz_kernel(
    const float* __restrict__ x,
    const float* __restrict__ Wi,
    const float* __restrict__ bh)
{
    extern __shared__ uint32_t smg[];
    uint32_t* a_hi = smg;                       // [64][A_STR] f16x2 (k-pairs)
    uint32_t* a_lo = a_hi + 64 * A_STR;
    uint32_t* b_hi = a_lo + 64 * A_STR;         // [64 kpair][B_STR n] f16x2
    uint32_t* b_lo = b_hi + 64 * B_STR;
    float*    sbh  = (float*)(b_lo + 64 * B_STR);   // [80] staged-order bias
    float*    sout = (float*)b_lo;              // epilogue staging (reuse b_lo)

    const int tid = threadIdx.x;
    const int m0  = blockIdx.x * BM;
    const int j0  = blockIdx.y * 20;

    // bias in staged order: p = jj*4 + gg  ->  bh[gg*100 + j0 + jj]
    if (tid < 80) sbh[tid] = bh[(tid & 3) * 100 + j0 + (tid >> 2)];

    // x tile: 64 rows x 64 k-pairs, split hi/lo
#pragma unroll
    for (int q = 0; q < 32; q++) {
        int idx = tid + q * 128;
        int r = idx >> 6, kp = idx & 63;
        float2 v = *(const float2*)(x + (size_t)(m0 + r) * DIN + 2 * kp);
        __half2 h = __floats2half2_rn(v.x, v.y);
        float2 hf = __half22float2(h);
        __half2 l = __floats2half2_rn((v.x - hf.x) * 2048.f,
                                      (v.y - hf.y) * 2048.f);
        a_hi[r * A_STR + kp] = *(uint32_t*)&h;
        a_lo[r * A_STR + kp] = *(uint32_t*)&l;
    }
    // Wi tile: 64 k-pairs x 80 local cols, split hi/lo
#pragma unroll
    for (int q = 0; q < 40; q++) {
        int idx = tid + q * 128;
        int c = idx % 80, kp = idx / 80;
        int gcol = (c / 20) * 100 + j0 + (c % 20);
        float f0 = Wi[(size_t)(2 * kp) * G4 + gcol];
        float f1 = Wi[(size_t)(2 * kp + 1) * G4 + gcol];
        __half2 h = __floats2half2_rn(f0, f1);
        float2 hf = __half22float2(h);
        __half2 l = __floats2half2_rn((f0 - hf.x) * 2048.f,
                                      (f1 - hf.y) * 2048.f);
        b_hi[kp * B_STR + c] = *(uint32_t*)&h;
        b_lo[kp * B_STR + c] = *(uint32_t*)&l;
    }
    __syncthreads();

    const int warp = tid >> 5, lane = tid & 31;
    const int gid = lane >> 2, tig = lane & 3;
    const int r0w = warp * 16;

    float accH[10][4], accL[10][4];
#pragma unroll
    for (int nt = 0; nt < 10; nt++)
#pragma unroll
        for (int q = 0; q < 4; q++) { accH[nt][q] = 0.f; accL[nt][q] = 0.f; }

    const uint32_t* ah_r0 = a_hi + (r0w + gid) * A_STR;
    const uint32_t* ah_r1 = a_hi + (r0w + gid + 8) * A_STR;
    const uint32_t* al_r0 = a_lo + (r0w + gid) * A_STR;
    const uint32_t* al_r1 = a_lo + (r0w + gid + 8) * A_STR;

#pragma unroll
    for (int kk = 0; kk < 8; kk++) {
        const int kp0 = kk * 8 + tig;       // k = 2*kp0, first k8 half
        const int kp1 = kp0 + 4;            // second k8 half
        uint32_t ah0 = ah_r0[kp0], ah1 = ah_r1[kp0];
        uint32_t ah2 = ah_r0[kp1], ah3 = ah_r1[kp1];
        uint32_t al0 = al_r0[kp0], al1 = al_r1[kp0];
        uint32_t al2 = al_r0[kp1], al3 = al_r1[kp1];
        const uint32_t* bh0p = b_hi + kp0 * B_STR + gid;
        const uint32_t* bh1p = b_hi + kp1 * B_STR + gid;
        const uint32_t* bl0p = b_lo + kp0 * B_STR + gid;
        const uint32_t* bl1p = b_lo + kp1 * B_STR + gid;
#pragma unroll
        for (int nt = 0; nt < 10; nt++) {
            uint32_t bh0 = bh0p[nt * 8], bh1 = bh1p[nt * 8];
            uint32_t bl0 = bl0p[nt * 8], bl1 = bl1p[nt * 8];
            mma_f16(accH[nt], ah0, ah1, ah2, ah3, bh0, bh1);
            mma_f16(accL[nt], ah0, ah1, ah2, ah3, bl0, bl1);
            mma_f16(accL[nt], al0, al1, al2, al3, bh0, bh1);
        }
    }
    __syncthreads();   // done reading b_lo; reuse as staging

    // stage accums into sout[row][p], p = (n'%20)*4 + n'/20
    const float INVL = 1.f / 2048.f;
#pragma unroll
    for (int nt = 0; nt < 10; nt++) {
        int n0c = nt * 8 + 2 * tig;
        int n1c = n0c + 1;
        int p0 = (n0c % 20) * 4 + n0c / 20;
        int p1 = (n1c % 20) * 4 + n1c / 20;
        sout[(r0w + gid) * SO_STR + p0]     = accH[nt][0] + accL[nt][0] * INVL;
        sout[(r0w + gid) * SO_STR + p1]     = accH[nt][1] + accL[nt][1] * INVL;
        sout[(r0w + gid + 8) * SO_STR + p0] = accH[nt][2] + accL[nt][2] * INVL;
        sout[(r0w + gid + 8) * SO_STR + p1] = accH[nt][3] + accL[nt][3] * INVL;
    }
    __syncthreads();

    // coalesced write-out: 64 rows x 20 float4 (+bias)
    float4* gout = (float4*)g_xz;
#pragma unroll
    for (int q = 0; q < 10; q++) {
        int i = tid + q * 128;
        int r = i / 20, c = i % 20;
        float4 v;
        v.x = sout[r * SO_STR + 4 * c + 0] + sbh[4 * c + 0];
        v.y = sout[r * SO_STR + 4 * c + 1] + sbh[4 * c + 1];
        v.z = sout[r * SO_STR + 4 * c + 2] + sbh[4 * c + 2];
        v.w = sout[r * SO_STR + 4 * c + 3] + sbh[4 * c + 3];
        gout[(size_t)(m0 + r) * 100 + 20 * blockIdx.y + c] = v;
    }
}

// ---------------------------------------------------------------------------
// Kernel 2: persistent LSTM recurrence + FUSED projection, f32x2.
// 128 CTAs x 16 rows, 400 THREADS: thread = (j = tid%100, rg = tid/100),
// owns 4 contiguous rows rg*4..rg*4+3. 12.5 warps/CTA (3.1/SMSP) for latency
// hiding; double-buffered h -> ONE barrier per step; fused rec(t)+proj(t-1).
// ---------------------------------------------------------------------------
__device__ __forceinline__ float sigf(float xv) {
    return __fdividef(1.f, 1.f + __expf(-xv));
}
__device__ __forceinline__ float tanh_f(float xv) {
    float e = __expf(2.f * xv);
    return 1.f - __fdividef(2.f, e + 1.f);
}

__global__ __launch_bounds__(400) void lstm_kernel(
    const float* __restrict__ Wh,
    const float* __restrict__ Wd,
    const float* __restrict__ bd,
    float* __restrict__ out)
{
    extern __shared__ float sm2[];
    float* Wq  = sm2;                 // 40000 floats
    float* Wdp = sm2 + 40000;         // 10000 floats
    float* hsm = sm2 + 50000;         // 2 x 1600 floats (double buffer)
    float* bds = sm2 + 53200;         // 100 floats

    const int tid = threadIdx.x;      // 0..399

    for (int i = tid; i < HID * G4; i += 400) {
        int k = i / G4, c = i - k * G4;
        int k2 = k >> 1, kl = k & 1;
        int g = c / HID, j = c - g * HID;
        int gp = g >> 1, gl = g & 1;
        Wq[(((k2 * 2 + gp) * HID + j) << 2) + gl * 2 + kl] = Wh[i];
    }
    for (int i = tid; i < HID * HID; i += 400) {
        int k = i / HID, j = i - k * HID;
        Wdp[(k >> 1) * (2 * HID) + j * 2 + (k & 1)] = Wd[i];
    }
    for (int i = tid; i < 16 * HID; i += 400) hsm[i] = 0.f;   // buffer 0 only
    if (tid < HID) bds[tid] = bd[tid];
    __syncthreads();

    const int j  = tid % HID;
    const int rg = tid / HID;                     // 0..3
    const int r0 = blockIdx.x * 16 + rg * 4;      // first of this thread's rows

    const uint32_t hbase = sptr(hsm) + (rg * 4) * (HID * 4);
    const uint32_t wqb   = sptr(Wq)  + j * 16;
    const uint32_t wdb   = sptr(Wdp) + j * 8;
    const float bj = bds[j];

    float cst[4];
#pragma unroll
    for (int i = 0; i < 4; i++) cst[i] = 0.f;

    // prefetched xz (current step): 4 rows x float4(4 gates)
    const float4* xzg = (const float4*)g_xz;
    float4 xzn[4];
#pragma unroll
    for (int i = 0; i < 4; i++)
        xzn[i] = __ldcs(xzg + ((size_t)(r0 + i) * TSTEPS) * HID + j);

    int cur = 0;
    for (int t = 0; t < TSTEPS; t++) {
        ull acc[4][4];
#pragma unroll
        for (int i = 0; i < 4; i++) {
            acc[i][0] = pack2(xzn[i].x, 0.f);
            acc[i][1] = pack2(xzn[i].y, 0.f);
            acc[i][2] = pack2(xzn[i].z, 0.f);
            acc[i][3] = pack2(xzn[i].w, 0.f);
        }
        if (t + 1 < TSTEPS) {
#pragma unroll
            for (int i = 0; i < 4; i++)
                xzn[i] = __ldcs(xzg + ((size_t)(r0 + i) * TSTEPS + (t + 1)) * HID + j);
        }

        ull pv[4];
#pragma unroll
        for (int i = 0; i < 4; i++) pv[i] = 0ull;

        const uint32_t hrow = hbase + cur * 6400;

        // FUSED loop: recurrence(t) + projection(t-1), one pass over h
#pragma unroll 5
        for (int k4 = 0; k4 < 25; k4++) {
            ull a[4][2];
#pragma unroll
            for (int i = 0; i < 4; i++)
                lds2(a[i][0], a[i][1], hrow + i * (HID * 4) + k4 * 16);
            ull bg[2][4];
#pragma unroll
            for (int kl = 0; kl < 2; kl++) {
                int k2 = 2 * k4 + kl;
                lds2(bg[kl][0], bg[kl][1], wqb + (k2 * 2 + 0) * (HID * 16));
                lds2(bg[kl][2], bg[kl][3], wqb + (k2 * 2 + 1) * (HID * 16));
            }
            const ull w0 = lds1(wdb + (2 * k4 + 0) * (HID * 8));
            const ull w1 = lds1(wdb + (2 * k4 + 1) * (HID * 8));
#pragma unroll
            for (int i = 0; i < 4; i++) {
#pragma unroll
                for (int g = 0; g < 4; g++) {
                    ffma2(acc[i][g], a[i][0], bg[0][g]);
                    ffma2(acc[i][g], a[i][1], bg[1][g]);
                }
                ffma2(pv[i], a[i][0], w0);
                ffma2(pv[i], a[i][1], w1);
            }
        }

        // store projection of step t-1 (h read above is post-step-(t-1))
        if (t > 0) {
#pragma unroll
            for (int i = 0; i < 4; i++) {
                const float v = hsum2(pv[i]) + bj;
                out[((size_t)(r0 + i) * TSTEPS + (t - 1)) * HID + j] =
                    fmaxf(v, 0.f);
            }
        }

        // gates (i, f, g, o)
        float hnew[4];
#pragma unroll
        for (int i = 0; i < 4; i++) {
            const float ig = sigf(hsum2(acc[i][0]));
            const float fg = sigf(hsum2(acc[i][1]));
            const float gg = tanh_f(hsum2(acc[i][2]));
            const float og = sigf(hsum2(acc[i][3]));
            const float c  = fg * cst[i] + ig * gg;
            cst[i]  = c;
            hnew[i] = og * tanh_f(c);
        }

        // write new h into the OTHER buffer; single barrier
        float* hn = hsm + (cur ^ 1) * 1600;
#pragma unroll
        for (int i = 0; i < 4; i++) hn[(rg * 4 + i) * HID + j] = hnew[i];
        __syncthreads();

        cur ^= 1;
    }

    // epilogue: projection of the final step (t = 249)
    {
        ull pv[4];
#pragma unroll
        for (int i = 0; i < 4; i++) pv[i] = 0ull;
        const uint32_t hrow = hbase + cur * 6400;
#pragma unroll 5
        for (int k4 = 0; k4 < 25; k4++) {
            ull a[4][2];
#pragma unroll
            for (int i = 0; i < 4; i++)
                lds2(a[i][0], a[i][1], hrow + i * (HID * 4) + k4 * 16);
            const ull w0 = lds1(wdb + (2 * k4 + 0) * (HID * 8));
            const ull w1 = lds1(wdb + (2 * k4 + 1) * (HID * 8));
#pragma unroll
            for (int i = 0; i < 4; i++) {
                ffma2(pv[i], a[i][0], w0);
                ffma2(pv[i], a[i][1], w1);
            }
        }
#pragma unroll
        for (int i = 0; i < 4; i++) {
            const float v = hsum2(pv[i]) + bj;
            out[((size_t)(r0 + i) * TSTEPS + (TSTEPS - 1)) * HID + j] =
                fmaxf(v, 0.f);
        }
    }
}

// ---------------------------------------------------------------------------
// Launch
// ---------------------------------------------------------------------------
extern "C" void kernel_launch(void* const* d_in, const int* in_sizes, int n_in,
                              void* d_out, int out_size)
{
    const float* x  = (const float*)d_in[0];   // [2048,250,128]
    const float* Wi = (const float*)d_in[1];   // [128,400]
    const float* Wh = (const float*)d_in[2];   // [100,400]
    const float* bh = (const float*)d_in[3];   // [400]
    const float* Wd = (const float*)d_in[4];   // [100,100]
    const float* bd = (const float*)d_in[5];   // [100]
    float* out = (float*)d_out;                // [2048,250,100]

    const int smem1 = (2 * 64 * A_STR + 2 * 64 * B_STR) * 4 + 80 * 4; // 88,384 B
    const int smem2 = 53300 * 4;                                      // 213,200 B
    cudaFuncSetAttribute(gemm_xz_kernel,
                         cudaFuncAttributeMaxDynamicSharedMemorySize, smem1);
    cudaFuncSetAttribute(lstm_kernel,
                         cudaFuncAttributeMaxDynamicSharedMemorySize, smem2);

    dim3 g1(MTOT / BM, 5);   // 8000 x 5
    gemm_xz_kernel<<<g1, 128, smem1>>>(x, Wi, bh);
    lstm_kernel<<<BATCH / 16, 400, smem2>>>(Wh, Wd, bd, out);
}

// round 11
// speedup vs baseline: 1.1453x; 1.0427x over previous
#include <cuda_runtime.h>
#include <cuda_fp16.h>
#include <cstdint>

typedef unsigned long long ull;

#define BATCH   2048
#define TSTEPS  250
#define DIN     128
#define HID     100
#define G4      400
#define MTOT    (BATCH*TSTEPS)

// Scratch for xz : GATE-INTERLEAVED layout [m][j][g]  (index = m*400 + j*4 + g)
__device__ float g_xz[(size_t)MTOT * G4];

// ---------------------------------------------------------------------------
// helpers
// ---------------------------------------------------------------------------
__device__ __forceinline__ uint32_t sptr(const void* p) {
    return (uint32_t)__cvta_generic_to_shared(p);
}
__device__ __forceinline__ void lds2(ull& a, ull& b, uint32_t addr) {
    asm volatile("ld.shared.v2.b64 {%0,%1}, [%2];" : "=l"(a), "=l"(b) : "r"(addr));
}
__device__ __forceinline__ ull lds1(uint32_t addr) {
    ull a; asm volatile("ld.shared.b64 %0, [%1];" : "=l"(a) : "r"(addr)); return a;
}
__device__ __forceinline__ void ffma2(ull& d, ull a, ull b) {
    asm volatile("fma.rn.f32x2 %0, %1, %2, %0;" : "+l"(d) : "l"(a), "l"(b));
}
__device__ __forceinline__ ull pack2(float lo, float hi) {
    ull r; asm("mov.b64 %0, {%1,%2};" : "=l"(r) : "f"(lo), "f"(hi)); return r;
}
__device__ __forceinline__ float hsum2(ull v) {
    float lo, hi; asm("mov.b64 {%0,%1}, %2;" : "=f"(lo), "=f"(hi) : "l"(v));
    return lo + hi;
}
__device__ __forceinline__ void mma_f16(float c[4], uint32_t a0, uint32_t a1,
                                        uint32_t a2, uint32_t a3,
                                        uint32_t b0, uint32_t b1) {
    asm volatile(
        "mma.sync.aligned.m16n8k16.row.col.f32.f16.f16.f32 "
        "{%0,%1,%2,%3}, {%4,%5,%6,%7}, {%8,%9}, {%0,%1,%2,%3};"
        : "+f"(c[0]), "+f"(c[1]), "+f"(c[2]), "+f"(c[3])
        : "r"(a0), "r"(a1), "r"(a2), "r"(a3), "r"(b0), "r"(b1));
}

// ---------------------------------------------------------------------------
// Kernel 1: xz = x@Wi + bh via fp16 split-3 mma.sync (UNCHANGED from R9,
// verified rel_err 3.8e-7):
//   a = ah + al/2048, b = bh + bl/2048; accH += ah*bh; accL += ah*bl + al*bh
// ---------------------------------------------------------------------------
#define BM 64
#define A_STR 68
#define B_STR 104
#define SO_STR 84

__global__ __launch_bounds__(128) void gemm_xz_kernel(
    const float* __restrict__ x,
    const float* __restrict__ Wi,
    const float* __restrict__ bh)
{
    extern __shared__ uint32_t smg[];
    uint32_t* a_hi = smg;                       // [64][A_STR] f16x2 (k-pairs)
    uint32_t* a_lo = a_hi + 64 * A_STR;
    uint32_t* b_hi = a_lo + 64 * A_STR;         // [64 kpair][B_STR n] f16x2
    uint32_t* b_lo = b_hi + 64 * B_STR;
    float*    sbh  = (float*)(b_lo + 64 * B_STR);
    float*    sout = (float*)b_lo;

    const int tid = threadIdx.x;
    const int m0  = blockIdx.x * BM;
    const int j0  = blockIdx.y * 20;

    if (tid < 80) sbh[tid] = bh[(tid & 3) * 100 + j0 + (tid >> 2)];

#pragma unroll
    for (int q = 0; q < 32; q++) {
        int idx = tid + q * 128;
        int r = idx >> 6, kp = idx & 63;
        float2 v = *(const float2*)(x + (size_t)(m0 + r) * DIN + 2 * kp);
        __half2 h = __floats2half2_rn(v.x, v.y);
        float2 hf = __half22float2(h);
        __half2 l = __floats2half2_rn((v.x - hf.x) * 2048.f,
                                      (v.y - hf.y) * 2048.f);
        a_hi[r * A_STR + kp] = *(uint32_t*)&h;
        a_lo[r * A_STR + kp] = *(uint32_t*)&l;
    }
#pragma unroll
    for (int q = 0; q < 40; q++) {
        int idx = tid + q * 128;
        int c = idx % 80, kp = idx / 80;
        int gcol = (c / 20) * 100 + j0 + (c % 20);
        float f0 = Wi[(size_t)(2 * kp) * G4 + gcol];
        float f1 = Wi[(size_t)(2 * kp + 1) * G4 + gcol];
        __half2 h = __floats2half2_rn(f0, f1);
        float2 hf = __half22float2(h);
        __half2 l = __floats2half2_rn((f0 - hf.x) * 2048.f,
                                      (f1 - hf.y) * 2048.f);
        b_hi[kp * B_STR + c] = *(uint32_t*)&h;
        b_lo[kp * B_STR + c] = *(uint32_t*)&l;
    }
    __syncthreads();

    const int warp = tid >> 5, lane = tid & 31;
    const int gid = lane >> 2, tig = lane & 3;
    const int r0w = warp * 16;

    float accH[10][4], accL[10][4];
#pragma unroll
    for (int nt = 0; nt < 10; nt++)
#pragma unroll
        for (int q = 0; q < 4; q++) { accH[nt][q] = 0.f; accL[nt][q] = 0.f; }

    const uint32_t* ah_r0 = a_hi + (r0w + gid) * A_STR;
    const uint32_t* ah_r1 = a_hi + (r0w + gid + 8) * A_STR;
    const uint32_t* al_r0 = a_lo + (r0w + gid) * A_STR;
    const uint32_t* al_r1 = a_lo + (r0w + gid + 8) * A_STR;

#pragma unroll
    for (int kk = 0; kk < 8; kk++) {
        const int kp0 = kk * 8 + tig;
        const int kp1 = kp0 + 4;
        uint32_t ah0 = ah_r0[kp0], ah1 = ah_r1[kp0];
        uint32_t ah2 = ah_r0[kp1], ah3 = ah_r1[kp1];
        uint32_t al0 = al_r0[kp0], al1 = al_r1[kp0];
        uint32_t al2 = al_r0[kp1], al3 = al_r1[kp1];
        const uint32_t* bh0p = b_hi + kp0 * B_STR + gid;
        const uint32_t* bh1p = b_hi + kp1 * B_STR + gid;
        const uint32_t* bl0p = b_lo + kp0 * B_STR + gid;
        const uint32_t* bl1p = b_lo + kp1 * B_STR + gid;
#pragma unroll
        for (int nt = 0; nt < 10; nt++) {
            uint32_t bh0 = bh0p[nt * 8], bh1 = bh1p[nt * 8];
            uint32_t bl0 = bl0p[nt * 8], bl1 = bl1p[nt * 8];
            mma_f16(accH[nt], ah0, ah1, ah2, ah3, bh0, bh1);
            mma_f16(accL[nt], ah0, ah1, ah2, ah3, bl0, bl1);
            mma_f16(accL[nt], al0, al1, al2, al3, bh0, bh1);
        }
    }
    __syncthreads();

    const float INVL = 1.f / 2048.f;
#pragma unroll
    for (int nt = 0; nt < 10; nt++) {
        int n0c = nt * 8 + 2 * tig;
        int n1c = n0c + 1;
        int p0 = (n0c % 20) * 4 + n0c / 20;
        int p1 = (n1c % 20) * 4 + n1c / 20;
        sout[(r0w + gid) * SO_STR + p0]     = accH[nt][0] + accL[nt][0] * INVL;
        sout[(r0w + gid) * SO_STR + p1]     = accH[nt][1] + accL[nt][1] * INVL;
        sout[(r0w + gid + 8) * SO_STR + p0] = accH[nt][2] + accL[nt][2] * INVL;
        sout[(r0w + gid + 8) * SO_STR + p1] = accH[nt][3] + accL[nt][3] * INVL;
    }
    __syncthreads();

    float4* gout = (float4*)g_xz;
#pragma unroll
    for (int q = 0; q < 10; q++) {
        int i = tid + q * 128;
        int r = i / 20, c = i % 20;
        float4 v;
        v.x = sout[r * SO_STR + 4 * c + 0] + sbh[4 * c + 0];
        v.y = sout[r * SO_STR + 4 * c + 1] + sbh[4 * c + 1];
        v.z = sout[r * SO_STR + 4 * c + 2] + sbh[4 * c + 2];
        v.w = sout[r * SO_STR + 4 * c + 3] + sbh[4 * c + 3];
        gout[(size_t)(m0 + r) * 100 + 20 * blockIdx.y + c] = v;
    }
}

// ---------------------------------------------------------------------------
// Kernel 2: persistent LSTM + fused projection, f32x2 — GROUP-DECOUPLED.
// 128 CTAs x 16 rows, 512 threads = 4 INDEPENDENT groups of 128 threads.
// Group g owns rows 4g..4g+3 (its own h, c, xz, out — fully disjoint), and
// syncs ONLY itself via named barrier (1+g). Groups share read-only weight
// smem and drift freely across the 250 steps, so each SMSP interleaves 4
// desynchronized streams instead of convoying on one CTA-wide barrier.
// Lanes with j>=100 (28 per group) are inert but participate in barriers.
// ---------------------------------------------------------------------------
__device__ __forceinline__ float sigf(float xv) {
    return __fdividef(1.f, 1.f + __expf(-xv));
}
__device__ __forceinline__ float tanh_f(float xv) {
    float e = __expf(2.f * xv);
    return 1.f - __fdividef(2.f, e + 1.f);
}
__device__ __forceinline__ void barg(int bar) {
    asm volatile("bar.sync %0, 128;" :: "r"(bar) : "memory");
}

__global__ __launch_bounds__(512, 1) void lstm_kernel(
    const float* __restrict__ Wh,
    const float* __restrict__ Wd,
    const float* __restrict__ bd,
    float* __restrict__ out)
{
    extern __shared__ float sm2[];
    float* Wq  = sm2;                 // 40000 floats
    float* Wdp = sm2 + 40000;         // 10000 floats
    float* hsm = sm2 + 50000;         // 2 x 1600 floats (double buffer)
    float* bds = sm2 + 53200;         // 100 floats

    const int tid = threadIdx.x;      // 0..511

    for (int i = tid; i < HID * G4; i += 512) {
        int k = i / G4, c = i - k * G4;
        int k2 = k >> 1, kl = k & 1;
        int g = c / HID, j = c - g * HID;
        int gp = g >> 1, gl = g & 1;
        Wq[(((k2 * 2 + gp) * HID + j) << 2) + gl * 2 + kl] = Wh[i];
    }
    for (int i = tid; i < HID * HID; i += 512) {
        int k = i / HID, j = i - k * HID;
        Wdp[(k >> 1) * (2 * HID) + j * 2 + (k & 1)] = Wd[i];
    }
    for (int i = tid; i < 16 * HID; i += 512) hsm[i] = 0.f;   // buffer 0 only
    if (tid < HID) bds[tid] = bd[tid];
    __syncthreads();                  // one full-CTA sync; groups free after

    const int gid    = tid >> 7;                  // group 0..3
    const int ji     = tid & 127;                 // lane in group
    const bool act   = (ji < HID);
    const int j      = act ? ji : 0;              // hidden column
    const int r0     = blockIdx.x * 16 + gid * 4; // group's first batch row
    const int mybar  = 1 + gid;

    const uint32_t hbase = sptr(hsm) + (gid * 4) * (HID * 4);
    const uint32_t wqb   = sptr(Wq)  + j * 16;
    const uint32_t wdb   = sptr(Wdp) + j * 8;
    const float bj = bds[j];

    float cst[4];
#pragma unroll
    for (int i = 0; i < 4; i++) cst[i] = 0.f;

    // prefetched xz (current step): 4 rows x float4(4 gates)
    const float4* xzg = (const float4*)g_xz;
    float4 xzn[4];
#pragma unroll
    for (int i = 0; i < 4; i++) {
        if (act)
            xzn[i] = __ldcs(xzg + ((size_t)(r0 + i) * TSTEPS) * HID + j);
        else
            xzn[i] = make_float4(0.f, 0.f, 0.f, 0.f);
    }

    int cur = 0;
    for (int t = 0; t < TSTEPS; t++) {
        ull acc[4][4];
#pragma unroll
        for (int i = 0; i < 4; i++) {
            acc[i][0] = pack2(xzn[i].x, 0.f);
            acc[i][1] = pack2(xzn[i].y, 0.f);
            acc[i][2] = pack2(xzn[i].z, 0.f);
            acc[i][3] = pack2(xzn[i].w, 0.f);
        }
        if (act && t + 1 < TSTEPS) {
#pragma unroll
            for (int i = 0; i < 4; i++)
                xzn[i] = __ldcs(xzg + ((size_t)(r0 + i) * TSTEPS + (t + 1)) * HID + j);
        }

        ull pv[4];
#pragma unroll
        for (int i = 0; i < 4; i++) pv[i] = 0ull;

        const uint32_t hrow = hbase + cur * 6400;

        // FUSED loop: recurrence(t) + projection(t-1), one pass over h
        if (act) {
#pragma unroll 5
            for (int k4 = 0; k4 < 25; k4++) {
                ull a[4][2];
#pragma unroll
                for (int i = 0; i < 4; i++)
                    lds2(a[i][0], a[i][1], hrow + i * (HID * 4) + k4 * 16);
                ull bg[2][4];
#pragma unroll
                for (int kl = 0; kl < 2; kl++) {
                    int k2 = 2 * k4 + kl;
                    lds2(bg[kl][0], bg[kl][1], wqb + (k2 * 2 + 0) * (HID * 16));
                    lds2(bg[kl][2], bg[kl][3], wqb + (k2 * 2 + 1) * (HID * 16));
                }
                const ull w0 = lds1(wdb + (2 * k4 + 0) * (HID * 8));
                const ull w1 = lds1(wdb + (2 * k4 + 1) * (HID * 8));
#pragma unroll
                for (int i = 0; i < 4; i++) {
#pragma unroll
                    for (int g = 0; g < 4; g++) {
                        ffma2(acc[i][g], a[i][0], bg[0][g]);
                        ffma2(acc[i][g], a[i][1], bg[1][g]);
                    }
                    ffma2(pv[i], a[i][0], w0);
                    ffma2(pv[i], a[i][1], w1);
                }
            }

            // store projection of step t-1 (h read above is post-step-(t-1))
            if (t > 0) {
#pragma unroll
                for (int i = 0; i < 4; i++) {
                    const float v = hsum2(pv[i]) + bj;
                    out[((size_t)(r0 + i) * TSTEPS + (t - 1)) * HID + j] =
                        fmaxf(v, 0.f);
                }
            }

            // gates (i, f, g, o)
            float hnew[4];
#pragma unroll
            for (int i = 0; i < 4; i++) {
                const float ig = sigf(hsum2(acc[i][0]));
                const float fg = sigf(hsum2(acc[i][1]));
                const float gg = tanh_f(hsum2(acc[i][2]));
                const float og = sigf(hsum2(acc[i][3]));
                const float c  = fg * cst[i] + ig * gg;
                cst[i]  = c;
                hnew[i] = og * tanh_f(c);
            }

            // write new h into the OTHER buffer
            float* hn = hsm + (cur ^ 1) * 1600;
#pragma unroll
            for (int i = 0; i < 4; i++) hn[(gid * 4 + i) * HID + j] = hnew[i];
        }

        barg(mybar);   // group-private barrier: my 4 rows' h complete
        cur ^= 1;
    }

    // epilogue: projection of the final step (t = 249)
    if (act) {
        ull pv[4];
#pragma unroll
        for (int i = 0; i < 4; i++) pv[i] = 0ull;
        const uint32_t hrow = hbase + cur * 6400;
#pragma unroll 5
        for (int k4 = 0; k4 < 25; k4++) {
            ull a[4][2];
#pragma unroll
            for (int i = 0; i < 4; i++)
                lds2(a[i][0], a[i][1], hrow + i * (HID * 4) + k4 * 16);
            const ull w0 = lds1(wdb + (2 * k4 + 0) * (HID * 8));
            const ull w1 = lds1(wdb + (2 * k4 + 1) * (HID * 8));
#pragma unroll
            for (int i = 0; i < 4; i++) {
                ffma2(pv[i], a[i][0], w0);
                ffma2(pv[i], a[i][1], w1);
            }
        }
#pragma unroll
        for (int i = 0; i < 4; i++) {
            const float v = hsum2(pv[i]) + bj;
            out[((size_t)(r0 + i) * TSTEPS + (TSTEPS - 1)) * HID + j] =
                fmaxf(v, 0.f);
        }
    }
}

// ---------------------------------------------------------------------------
// Launch
// ---------------------------------------------------------------------------
extern "C" void kernel_launch(void* const* d_in, const int* in_sizes, int n_in,
                              void* d_out, int out_size)
{
    const float* x  = (const float*)d_in[0];   // [2048,250,128]
    const float* Wi = (const float*)d_in[1];   // [128,400]
    const float* Wh = (const float*)d_in[2];   // [100,400]
    const float* bh = (const float*)d_in[3];   // [400]
    const float* Wd = (const float*)d_in[4];   // [100,100]
    const float* bd = (const float*)d_in[5];   // [100]
    float* out = (float*)d_out;                // [2048,250,100]

    const int smem1 = (2 * 64 * A_STR + 2 * 64 * B_STR) * 4 + 80 * 4; // 88,384 B
    const int smem2 = 53300 * 4;                                      // 213,200 B
    cudaFuncSetAttribute(gemm_xz_kernel,
                         cudaFuncAttributeMaxDynamicSharedMemorySize, smem1);
    cudaFuncSetAttribute(lstm_kernel,
                         cudaFuncAttributeMaxDynamicSharedMemorySize, smem2);

    dim3 g1(MTOT / BM, 5);   // 8000 x 5
    gemm_xz_kernel<<<g1, 128, smem1>>>(x, Wi, bh);
    lstm_kernel<<<BATCH / 16, 512, smem2>>>(Wh, Wd, bd, out);
}

// round 12
// speedup vs baseline: 1.2960x; 1.1316x over previous
#include <cuda_runtime.h>
#include <cuda_fp16.h>
#include <cstdint>

typedef unsigned long long ull;

#define BATCH   2048
#define TSTEPS  250
#define DIN     128
#define HID     100
#define G4      400
#define MTOT    (BATCH*TSTEPS)

// Scratch for xz : GATE-INTERLEAVED layout [m][j][g]  (index = m*400 + j*4 + g)
__device__ float g_xz[(size_t)MTOT * G4];
// Pre-split Wi (written once per launch by wi_split_kernel):
// [kp][gcol] f16x2 of the k-pair (2*kp, 2*kp+1), hi and scaled-lo parts.
__device__ uint32_t g_wi_hi[64 * G4];
__device__ uint32_t g_wi_lo[64 * G4];

// ---------------------------------------------------------------------------
// helpers
// ---------------------------------------------------------------------------
__device__ __forceinline__ uint32_t sptr(const void* p) {
    return (uint32_t)__cvta_generic_to_shared(p);
}
__device__ __forceinline__ void lds2(ull& a, ull& b, uint32_t addr) {
    asm volatile("ld.shared.v2.b64 {%0,%1}, [%2];" : "=l"(a), "=l"(b) : "r"(addr));
}
__device__ __forceinline__ ull lds1(uint32_t addr) {
    ull a; asm volatile("ld.shared.b64 %0, [%1];" : "=l"(a) : "r"(addr)); return a;
}
__device__ __forceinline__ void ffma2(ull& d, ull a, ull b) {
    asm volatile("fma.rn.f32x2 %0, %1, %2, %0;" : "+l"(d) : "l"(a), "l"(b));
}
__device__ __forceinline__ ull pack2(float lo, float hi) {
    ull r; asm("mov.b64 %0, {%1,%2};" : "=l"(r) : "f"(lo), "f"(hi)); return r;
}
__device__ __forceinline__ float hsum2(ull v) {
    float lo, hi; asm("mov.b64 {%0,%1}, %2;" : "=f"(lo), "=f"(hi) : "l"(v));
    return lo + hi;
}
__device__ __forceinline__ void cpasync16(uint32_t dst, const void* src) {
    asm volatile("cp.async.ca.shared.global [%0], [%1], 16;" :: "r"(dst), "l"(src));
}
__device__ __forceinline__ void mma_f16(float c[4], uint32_t a0, uint32_t a1,
                                        uint32_t a2, uint32_t a3,
                                        uint32_t b0, uint32_t b1) {
    asm volatile(
        "mma.sync.aligned.m16n8k16.row.col.f32.f16.f16.f32 "
        "{%0,%1,%2,%3}, {%4,%5,%6,%7}, {%8,%9}, {%0,%1,%2,%3};"
        : "+f"(c[0]), "+f"(c[1]), "+f"(c[2]), "+f"(c[3])
        : "r"(a0), "r"(a1), "r"(a2), "r"(a3), "r"(b0), "r"(b1));
}

// ---------------------------------------------------------------------------
// Kernel 0: pre-split Wi into hi/lo f16x2 k-pair layout (once per launch).
// g_wi_{hi,lo}[kp * 400 + gcol]; same split math the gemm did per-CTA before.
// ---------------------------------------------------------------------------
__global__ __launch_bounds__(256) void wi_split_kernel(
    const float* __restrict__ Wi)
{
    int i = blockIdx.x * 256 + threadIdx.x;     // over 64*400 k-pair x col
    if (i >= 64 * G4) return;
    int kp = i / G4, c = i - kp * G4;
    float f0 = Wi[(size_t)(2 * kp) * G4 + c];
    float f1 = Wi[(size_t)(2 * kp + 1) * G4 + c];
    __half2 h = __floats2half2_rn(f0, f1);
    float2 hf = __half22float2(h);
    __half2 l = __floats2half2_rn((f0 - hf.x) * 2048.f,
                                  (f1 - hf.y) * 2048.f);
    g_wi_hi[i] = *(uint32_t*)&h;
    g_wi_lo[i] = *(uint32_t*)&l;
}

// ---------------------------------------------------------------------------
// Kernel 1: xz = x@Wi + bh via fp16 split-3 mma.sync (numerics identical to
// R9/R10, verified rel_err 3.8e-7). Wi tiles now arrive PRE-SPLIT via
// cp.async (issued first, overlapping the x split). Only the prologue changed.
// ---------------------------------------------------------------------------
#define BM 64
#define A_STR 68
#define B_STR 104
#define SO_STR 84

__global__ __launch_bounds__(128) void gemm_xz_kernel(
    const float* __restrict__ x,
    const float* __restrict__ bh)
{
    extern __shared__ uint32_t smg[];
    uint32_t* a_hi = smg;                       // [64][A_STR] f16x2 (k-pairs)
    uint32_t* a_lo = a_hi + 64 * A_STR;
    uint32_t* b_hi = a_lo + 64 * A_STR;         // [64 kpair][B_STR n] f16x2
    uint32_t* b_lo = b_hi + 64 * B_STR;
    float*    sbh  = (float*)(b_lo + 64 * B_STR);
    float*    sout = (float*)b_lo;

    const int tid = threadIdx.x;
    const int m0  = blockIdx.x * BM;
    const int j0  = blockIdx.y * 20;

    if (tid < 80) sbh[tid] = bh[(tid & 3) * 100 + j0 + (tid >> 2)];

    // Wi tiles: pure cp.async copies of pre-split data. 1280 16B-chunks per
    // buffer: chunk = (kp, gate g, cc): 4 uint32 from g_wi_*[kp*400 + g*100 +
    // j0 + cc*4] -> b_*[kp*B_STR + g*20 + cc*4]. Issued FIRST to overlap the
    // x-split below.
    {
        const uint32_t bhs = sptr(b_hi);
        const uint32_t bls = sptr(b_lo);
#pragma unroll
        for (int q = 0; q < 10; q++) {
            int idx = tid + q * 128;            // 0..1279
            int kp = idx / 20, rem = idx % 20;
            int g = rem / 5, cc = rem % 5;
            int soff = kp * G4 + g * 100 + j0 + cc * 4;
            int doff = (kp * B_STR + g * 20 + cc * 4) * 4;
            cpasync16(bhs + doff, g_wi_hi + soff);
            cpasync16(bls + doff, g_wi_lo + soff);
        }
        asm volatile("cp.async.commit_group;");
    }

    // x tile: 64 rows x 64 k-pairs, split hi/lo (runs while cp.async fly)
#pragma unroll
    for (int q = 0; q < 32; q++) {
        int idx = tid + q * 128;
        int r = idx >> 6, kp = idx & 63;
        float2 v = *(const float2*)(x + (size_t)(m0 + r) * DIN + 2 * kp);
        __half2 h = __floats2half2_rn(v.x, v.y);
        float2 hf = __half22float2(h);
        __half2 l = __floats2half2_rn((v.x - hf.x) * 2048.f,
                                      (v.y - hf.y) * 2048.f);
        a_hi[r * A_STR + kp] = *(uint32_t*)&h;
        a_lo[r * A_STR + kp] = *(uint32_t*)&l;
    }
    asm volatile("cp.async.wait_group 0;");
    __syncthreads();

    const int warp = tid >> 5, lane = tid & 31;
    const int gid = lane >> 2, tig = lane & 3;
    const int r0w = warp * 16;

    float accH[10][4], accL[10][4];
#pragma unroll
    for (int nt = 0; nt < 10; nt++)
#pragma unroll
        for (int q = 0; q < 4; q++) { accH[nt][q] = 0.f; accL[nt][q] = 0.f; }

    const uint32_t* ah_r0 = a_hi + (r0w + gid) * A_STR;
    const uint32_t* ah_r1 = a_hi + (r0w + gid + 8) * A_STR;
    const uint32_t* al_r0 = a_lo + (r0w + gid) * A_STR;
    const uint32_t* al_r1 = a_lo + (r0w + gid + 8) * A_STR;

#pragma unroll
    for (int kk = 0; kk < 8; kk++) {
        const int kp0 = kk * 8 + tig;
        const int kp1 = kp0 + 4;
        uint32_t ah0 = ah_r0[kp0], ah1 = ah_r1[kp0];
        uint32_t ah2 = ah_r0[kp1], ah3 = ah_r1[kp1];
        uint32_t al0 = al_r0[kp0], al1 = al_r1[kp0];
        uint32_t al2 = al_r0[kp1], al3 = al_r1[kp1];
        const uint32_t* bh0p = b_hi + kp0 * B_STR + gid;
        const uint32_t* bh1p = b_hi + kp1 * B_STR + gid;
        const uint32_t* bl0p = b_lo + kp0 * B_STR + gid;
        const uint32_t* bl1p = b_lo + kp1 * B_STR + gid;
#pragma unroll
        for (int nt = 0; nt < 10; nt++) {
            uint32_t bh0 = bh0p[nt * 8], bh1 = bh1p[nt * 8];
            uint32_t bl0 = bl0p[nt * 8], bl1 = bl1p[nt * 8];
            mma_f16(accH[nt], ah0, ah1, ah2, ah3, bh0, bh1);
            mma_f16(accL[nt], ah0, ah1, ah2, ah3, bl0, bl1);
            mma_f16(accL[nt], al0, al1, al2, al3, bh0, bh1);
        }
    }
    __syncthreads();

    const float INVL = 1.f / 2048.f;
#pragma unroll
    for (int nt = 0; nt < 10; nt++) {
        int n0c = nt * 8 + 2 * tig;
        int n1c = n0c + 1;
        int p0 = (n0c % 20) * 4 + n0c / 20;
        int p1 = (n1c % 20) * 4 + n1c / 20;
        sout[(r0w + gid) * SO_STR + p0]     = accH[nt][0] + accL[nt][0] * INVL;
        sout[(r0w + gid) * SO_STR + p1]     = accH[nt][1] + accL[nt][1] * INVL;
        sout[(r0w + gid + 8) * SO_STR + p0] = accH[nt][2] + accL[nt][2] * INVL;
        sout[(r0w + gid + 8) * SO_STR + p1] = accH[nt][3] + accL[nt][3] * INVL;
    }
    __syncthreads();

    float4* gout = (float4*)g_xz;
#pragma unroll
    for (int q = 0; q < 10; q++) {
        int i = tid + q * 128;
        int r = i / 20, c = i % 20;
        float4 v;
        v.x = sout[r * SO_STR + 4 * c + 0] + sbh[4 * c + 0];
        v.y = sout[r * SO_STR + 4 * c + 1] + sbh[4 * c + 1];
        v.z = sout[r * SO_STR + 4 * c + 2] + sbh[4 * c + 2];
        v.w = sout[r * SO_STR + 4 * c + 3] + sbh[4 * c + 3];
        gout[(size_t)(m0 + r) * 100 + 20 * blockIdx.y + c] = v;
    }
}

// ---------------------------------------------------------------------------
// Kernel 2: persistent LSTM + fused projection, f32x2 — GROUP-DECOUPLED.
// (Byte-identical to R10: 512 thr = 4 independent 128-thread groups, named
// barriers, double-buffered h, fused rec(t)+proj(t-1).)
// ---------------------------------------------------------------------------
__device__ __forceinline__ float sigf(float xv) {
    return __fdividef(1.f, 1.f + __expf(-xv));
}
__device__ __forceinline__ float tanh_f(float xv) {
    float e = __expf(2.f * xv);
    return 1.f - __fdividef(2.f, e + 1.f);
}
__device__ __forceinline__ void barg(int bar) {
    asm volatile("bar.sync %0, 128;" :: "r"(bar) : "memory");
}

__global__ __launch_bounds__(512, 1) void lstm_kernel(
    const float* __restrict__ Wh,
    const float* __restrict__ Wd,
    const float* __restrict__ bd,
    float* __restrict__ out)
{
    extern __shared__ float sm2[];
    float* Wq  = sm2;                 // 40000 floats
    float* Wdp = sm2 + 40000;         // 10000 floats
    float* hsm = sm2 + 50000;         // 2 x 1600 floats (double buffer)
    float* bds = sm2 + 53200;         // 100 floats

    const int tid = threadIdx.x;      // 0..511

    for (int i = tid; i < HID * G4; i += 512) {
        int k = i / G4, c = i - k * G4;
        int k2 = k >> 1, kl = k & 1;
        int g = c / HID, j = c - g * HID;
        int gp = g >> 1, gl = g & 1;
        Wq[(((k2 * 2 + gp) * HID + j) << 2) + gl * 2 + kl] = Wh[i];
    }
    for (int i = tid; i < HID * HID; i += 512) {
        int k = i / HID, j = i - k * HID;
        Wdp[(k >> 1) * (2 * HID) + j * 2 + (k & 1)] = Wd[i];
    }
    for (int i = tid; i < 16 * HID; i += 512) hsm[i] = 0.f;   // buffer 0 only
    if (tid < HID) bds[tid] = bd[tid];
    __syncthreads();                  // one full-CTA sync; groups free after

    const int gid    = tid >> 7;                  // group 0..3
    const int ji     = tid & 127;                 // lane in group
    const bool act   = (ji < HID);
    const int j      = act ? ji : 0;              // hidden column
    const int r0     = blockIdx.x * 16 + gid * 4; // group's first batch row
    const int mybar  = 1 + gid;

    const uint32_t hbase = sptr(hsm) + (gid * 4) * (HID * 4);
    const uint32_t wqb   = sptr(Wq)  + j * 16;
    const uint32_t wdb   = sptr(Wdp) + j * 8;
    const float bj = bds[j];

    float cst[4];
#pragma unroll
    for (int i = 0; i < 4; i++) cst[i] = 0.f;

    // prefetched xz (current step): 4 rows x float4(4 gates)
    const float4* xzg = (const float4*)g_xz;
    float4 xzn[4];
#pragma unroll
    for (int i = 0; i < 4; i++) {
        if (act)
            xzn[i] = __ldcs(xzg + ((size_t)(r0 + i) * TSTEPS) * HID + j);
        else
            xzn[i] = make_float4(0.f, 0.f, 0.f, 0.f);
    }

    int cur = 0;
    for (int t = 0; t < TSTEPS; t++) {
        ull acc[4][4];
#pragma unroll
        for (int i = 0; i < 4; i++) {
            acc[i][0] = pack2(xzn[i].x, 0.f);
            acc[i][1] = pack2(xzn[i].y, 0.f);
            acc[i][2] = pack2(xzn[i].z, 0.f);
            acc[i][3] = pack2(xzn[i].w, 0.f);
        }
        if (act && t + 1 < TSTEPS) {
#pragma unroll
            for (int i = 0; i < 4; i++)
                xzn[i] = __ldcs(xzg + ((size_t)(r0 + i) * TSTEPS + (t + 1)) * HID + j);
        }

        ull pv[4];
#pragma unroll
        for (int i = 0; i < 4; i++) pv[i] = 0ull;

        const uint32_t hrow = hbase + cur * 6400;

        // FUSED loop: recurrence(t) + projection(t-1), one pass over h
        if (act) {
#pragma unroll 5
            for (int k4 = 0; k4 < 25; k4++) {
                ull a[4][2];
#pragma unroll
                for (int i = 0; i < 4; i++)
                    lds2(a[i][0], a[i][1], hrow + i * (HID * 4) + k4 * 16);
                ull bg[2][4];
#pragma unroll
                for (int kl = 0; kl < 2; kl++) {
                    int k2 = 2 * k4 + kl;
                    lds2(bg[kl][0], bg[kl][1], wqb + (k2 * 2 + 0) * (HID * 16));
                    lds2(bg[kl][2], bg[kl][3], wqb + (k2 * 2 + 1) * (HID * 16));
                }
                const ull w0 = lds1(wdb + (2 * k4 + 0) * (HID * 8));
                const ull w1 = lds1(wdb + (2 * k4 + 1) * (HID * 8));
#pragma unroll
                for (int i = 0; i < 4; i++) {
#pragma unroll
                    for (int g = 0; g < 4; g++) {
                        ffma2(acc[i][g], a[i][0], bg[0][g]);
                        ffma2(acc[i][g], a[i][1], bg[1][g]);
                    }
                    ffma2(pv[i], a[i][0], w0);
                    ffma2(pv[i], a[i][1], w1);
                }
            }

            // store projection of step t-1 (h read above is post-step-(t-1))
            if (t > 0) {
#pragma unroll
                for (int i = 0; i < 4; i++) {
                    const float v = hsum2(pv[i]) + bj;
                    out[((size_t)(r0 + i) * TSTEPS + (t - 1)) * HID + j] =
                        fmaxf(v, 0.f);
                }
            }

            // gates (i, f, g, o)
            float hnew[4];
#pragma unroll
            for (int i = 0; i < 4; i++) {
                const float ig = sigf(hsum2(acc[i][0]));
                const float fg = sigf(hsum2(acc[i][1]));
                const float gg = tanh_f(hsum2(acc[i][2]));
                const float og = sigf(hsum2(acc[i][3]));
                const float c  = fg * cst[i] + ig * gg;
                cst[i]  = c;
                hnew[i] = og * tanh_f(c);
            }

            // write new h into the OTHER buffer
            float* hn = hsm + (cur ^ 1) * 1600;
#pragma unroll
            for (int i = 0; i < 4; i++) hn[(gid * 4 + i) * HID + j] = hnew[i];
        }

        barg(mybar);   // group-private barrier: my 4 rows' h complete
        cur ^= 1;
    }

    // epilogue: projection of the final step (t = 249)
    if (act) {
        ull pv[4];
#pragma unroll
        for (int i = 0; i < 4; i++) pv[i] = 0ull;
        const uint32_t hrow = hbase + cur * 6400;
#pragma unroll 5
        for (int k4 = 0; k4 < 25; k4++) {
            ull a[4][2];
#pragma unroll
            for (int i = 0; i < 4; i++)
                lds2(a[i][0], a[i][1], hrow + i * (HID * 4) + k4 * 16);
            const ull w0 = lds1(wdb + (2 * k4 + 0) * (HID * 8));
            const ull w1 = lds1(wdb + (2 * k4 + 1) * (HID * 8));
#pragma unroll
            for (int i = 0; i < 4; i++) {
                ffma2(pv[i], a[i][0], w0);
                ffma2(pv[i], a[i][1], w1);
            }
        }
#pragma unroll
        for (int i = 0; i < 4; i++) {
            const float v = hsum2(pv[i]) + bj;
            out[((size_t)(r0 + i) * TSTEPS + (TSTEPS - 1)) * HID + j] =
                fmaxf(v, 0.f);
        }
    }
}

// ---------------------------------------------------------------------------
// Launch
// ---------------------------------------------------------------------------
extern "C" void kernel_launch(void* const* d_in, const int* in_sizes, int n_in,
                              void* d_out, int out_size)
{
    const float* x  = (const float*)d_in[0];   // [2048,250,128]
    const float* Wi = (const float*)d_in[1];   // [128,400]
    const float* Wh = (const float*)d_in[2];   // [100,400]
    const float* bh = (const float*)d_in[3];   // [400]
    const float* Wd = (const float*)d_in[4];   // [100,100]
    const float* bd = (const float*)d_in[5];   // [100]
    float* out = (float*)d_out;                // [2048,250,100]

    const int smem1 = (2 * 64 * A_STR + 2 * 64 * B_STR) * 4 + 80 * 4; // 88,384 B
    const int smem2 = 53300 * 4;                                      // 213,200 B
    cudaFuncSetAttribute(gemm_xz_kernel,
                         cudaFuncAttributeMaxDynamicSharedMemorySize, smem1);
    cudaFuncSetAttribute(lstm_kernel,
                         cudaFuncAttributeMaxDynamicSharedMemorySize, smem2);

    wi_split_kernel<<<(64 * G4 + 255) / 256, 256>>>(Wi);
    dim3 g1(MTOT / BM, 5);   // 8000 x 5
    gemm_xz_kernel<<<g1, 128, smem1>>>(x, bh);
    lstm_kernel<<<BATCH / 16, 512, smem2>>>(Wh, Wd, bd, out);
}

// round 13
// speedup vs baseline: 1.9193x; 1.4809x over previous
#include <cuda_runtime.h>
#include <cuda_fp16.h>
#include <cstdint>

typedef unsigned long long ull;

#define BATCH   2048
#define TSTEPS  250
#define DIN     128
#define HID     100
#define G4      400
#define MTOT    (BATCH*TSTEPS)

// Scratch for xz : GATE-INTERLEAVED layout [m][j][g]  (index = m*400 + j*4 + g)
__device__ float g_xz[(size_t)MTOT * G4];
// Pre-split Wi (written once per launch by wi_split_kernel)
__device__ uint32_t g_wi_hi[64 * G4];
__device__ uint32_t g_wi_lo[64 * G4];

// ---------------------------------------------------------------------------
// helpers
// ---------------------------------------------------------------------------
__device__ __forceinline__ uint32_t sptr(const void* p) {
    return (uint32_t)__cvta_generic_to_shared(p);
}
__device__ __forceinline__ void cpasync16(uint32_t dst, const void* src) {
    asm volatile("cp.async.ca.shared.global [%0], [%1], 16;" :: "r"(dst), "l"(src));
}
__device__ __forceinline__ void mma_f16(float c[4], uint32_t a0, uint32_t a1,
                                        uint32_t a2, uint32_t a3,
                                        uint32_t b0, uint32_t b1) {
    asm volatile(
        "mma.sync.aligned.m16n8k16.row.col.f32.f16.f16.f32 "
        "{%0,%1,%2,%3}, {%4,%5,%6,%7}, {%8,%9}, {%0,%1,%2,%3};"
        : "+f"(c[0]), "+f"(c[1]), "+f"(c[2]), "+f"(c[3])
        : "r"(a0), "r"(a1), "r"(a2), "r"(a3), "r"(b0), "r"(b1));
}
__device__ __forceinline__ void mma_f16_k8(float c[4], uint32_t a0, uint32_t a1,
                                           uint32_t b0) {
    asm volatile(
        "mma.sync.aligned.m16n8k8.row.col.f32.f16.f16.f32 "
        "{%0,%1,%2,%3}, {%4,%5}, {%6}, {%0,%1,%2,%3};"
        : "+f"(c[0]), "+f"(c[1]), "+f"(c[2]), "+f"(c[3])
        : "r"(a0), "r"(a1), "r"(b0));
}
__device__ __forceinline__ void ldmx4(uint32_t& r0, uint32_t& r1,
                                      uint32_t& r2, uint32_t& r3, uint32_t a) {
    asm volatile("ldmatrix.sync.aligned.m8n8.x4.shared.b16 {%0,%1,%2,%3}, [%4];"
        : "=r"(r0), "=r"(r1), "=r"(r2), "=r"(r3) : "r"(a));
}
__device__ __forceinline__ void ldmx2(uint32_t& r0, uint32_t& r1, uint32_t a) {
    asm volatile("ldmatrix.sync.aligned.m8n8.x2.shared.b16 {%0,%1}, [%2];"
        : "=r"(r0), "=r"(r1) : "r"(a));
}

// ---------------------------------------------------------------------------
// Kernel 0: pre-split Wi into hi/lo f16x2 k-pair layout (once per launch).
// ---------------------------------------------------------------------------
__global__ __launch_bounds__(256) void wi_split_kernel(
    const float* __restrict__ Wi)
{
    int i = blockIdx.x * 256 + threadIdx.x;
    if (i >= 64 * G4) return;
    int kp = i / G4, c = i - kp * G4;
    float f0 = Wi[(size_t)(2 * kp) * G4 + c];
    float f1 = Wi[(size_t)(2 * kp + 1) * G4 + c];
    __half2 h = __floats2half2_rn(f0, f1);
    float2 hf = __half22float2(h);
    __half2 l = __floats2half2_rn((f0 - hf.x) * 2048.f,
                                  (f1 - hf.y) * 2048.f);
    g_wi_hi[i] = *(uint32_t*)&h;
    g_wi_lo[i] = *(uint32_t*)&l;
}

// ---------------------------------------------------------------------------
// Kernel 1: xz = x@Wi + bh via fp16 split-3 mma.sync (byte-identical to R11,
// verified rel_err 3.778e-7).
// ---------------------------------------------------------------------------
#define BM 64
#define A_STR 68
#define B_STR 104
#define SO_STR 84

__global__ __launch_bounds__(128) void gemm_xz_kernel(
    const float* __restrict__ x,
    const float* __restrict__ bh)
{
    extern __shared__ uint32_t smg[];
    uint32_t* a_hi = smg;
    uint32_t* a_lo = a_hi + 64 * A_STR;
    uint32_t* b_hi = a_lo + 64 * A_STR;
    uint32_t* b_lo = b_hi + 64 * B_STR;
    float*    sbh  = (float*)(b_lo + 64 * B_STR);
    float*    sout = (float*)b_lo;

    const int tid = threadIdx.x;
    const int m0  = blockIdx.x * BM;
    const int j0  = blockIdx.y * 20;

    if (tid < 80) sbh[tid] = bh[(tid & 3) * 100 + j0 + (tid >> 2)];

    {
        const uint32_t bhs = sptr(b_hi);
        const uint32_t bls = sptr(b_lo);
#pragma unroll
        for (int q = 0; q < 10; q++) {
            int idx = tid + q * 128;
            int kp = idx / 20, rem = idx % 20;
            int g = rem / 5, cc = rem % 5;
            int soff = kp * G4 + g * 100 + j0 + cc * 4;
            int doff = (kp * B_STR + g * 20 + cc * 4) * 4;
            cpasync16(bhs + doff, g_wi_hi + soff);
            cpasync16(bls + doff, g_wi_lo + soff);
        }
        asm volatile("cp.async.commit_group;");
    }

#pragma unroll
    for (int q = 0; q < 32; q++) {
        int idx = tid + q * 128;
        int r = idx >> 6, kp = idx & 63;
        float2 v = *(const float2*)(x + (size_t)(m0 + r) * DIN + 2 * kp);
        __half2 h = __floats2half2_rn(v.x, v.y);
        float2 hf = __half22float2(h);
        __half2 l = __floats2half2_rn((v.x - hf.x) * 2048.f,
                                      (v.y - hf.y) * 2048.f);
        a_hi[r * A_STR + kp] = *(uint32_t*)&h;
        a_lo[r * A_STR + kp] = *(uint32_t*)&l;
    }
    asm volatile("cp.async.wait_group 0;");
    __syncthreads();

    const int warp = tid >> 5, lane = tid & 31;
    const int gid = lane >> 2, tig = lane & 3;
    const int r0w = warp * 16;

    float accH[10][4], accL[10][4];
#pragma unroll
    for (int nt = 0; nt < 10; nt++)
#pragma unroll
        for (int q = 0; q < 4; q++) { accH[nt][q] = 0.f; accL[nt][q] = 0.f; }

    const uint32_t* ah_r0 = a_hi + (r0w + gid) * A_STR;
    const uint32_t* ah_r1 = a_hi + (r0w + gid + 8) * A_STR;
    const uint32_t* al_r0 = a_lo + (r0w + gid) * A_STR;
    const uint32_t* al_r1 = a_lo + (r0w + gid + 8) * A_STR;

#pragma unroll
    for (int kk = 0; kk < 8; kk++) {
        const int kp0 = kk * 8 + tig;
        const int kp1 = kp0 + 4;
        uint32_t ah0 = ah_r0[kp0], ah1 = ah_r1[kp0];
        uint32_t ah2 = ah_r0[kp1], ah3 = ah_r1[kp1];
        uint32_t al0 = al_r0[kp0], al1 = al_r1[kp0];
        uint32_t al2 = al_r0[kp1], al3 = al_r1[kp1];
        const uint32_t* bh0p = b_hi + kp0 * B_STR + gid;
        const uint32_t* bh1p = b_hi + kp1 * B_STR + gid;
        const uint32_t* bl0p = b_lo + kp0 * B_STR + gid;
        const uint32_t* bl1p = b_lo + kp1 * B_STR + gid;
#pragma unroll
        for (int nt = 0; nt < 10; nt++) {
            uint32_t bh0 = bh0p[nt * 8], bh1 = bh1p[nt * 8];
            uint32_t bl0 = bl0p[nt * 8], bl1 = bl1p[nt * 8];
            mma_f16(accH[nt], ah0, ah1, ah2, ah3, bh0, bh1);
            mma_f16(accL[nt], ah0, ah1, ah2, ah3, bl0, bl1);
            mma_f16(accL[nt], al0, al1, al2, al3, bh0, bh1);
        }
    }
    __syncthreads();

    const float INVL = 1.f / 2048.f;
#pragma unroll
    for (int nt = 0; nt < 10; nt++) {
        int n0c = nt * 8 + 2 * tig;
        int n1c = n0c + 1;
        int p0 = (n0c % 20) * 4 + n0c / 20;
        int p1 = (n1c % 20) * 4 + n1c / 20;
        sout[(r0w + gid) * SO_STR + p0]     = accH[nt][0] + accL[nt][0] * INVL;
        sout[(r0w + gid) * SO_STR + p1]     = accH[nt][1] + accL[nt][1] * INVL;
        sout[(r0w + gid + 8) * SO_STR + p0] = accH[nt][2] + accL[nt][2] * INVL;
        sout[(r0w + gid + 8) * SO_STR + p1] = accH[nt][3] + accL[nt][3] * INVL;
    }
    __syncthreads();

    float4* gout = (float4*)g_xz;
#pragma unroll
    for (int q = 0; q < 10; q++) {
        int i = tid + q * 128;
        int r = i / 20, c = i % 20;
        float4 v;
        v.x = sout[r * SO_STR + 4 * c + 0] + sbh[4 * c + 0];
        v.y = sout[r * SO_STR + 4 * c + 1] + sbh[4 * c + 1];
        v.z = sout[r * SO_STR + 4 * c + 2] + sbh[4 * c + 2];
        v.w = sout[r * SO_STR + 4 * c + 3] + sbh[4 * c + 3];
        gout[(size_t)(m0 + r) * 100 + 20 * blockIdx.y + c] = v;
    }
}

// ---------------------------------------------------------------------------
// Kernel 2: TENSORIZED persistent LSTM + fused projection.
// 128 CTAs x 16 batch rows (M=16), 320 threads (10 warps).
// Per step: Z[16x400] = H @ Wh via m16n8k16 fp16 split-3 (hi/lo, lo x2048);
// projection H @ Wd fused into the same k-loop (reuses A fragments = h(t-1)).
// Wh columns GATE-INTERLEAVED (col' = 4j+g) so one 8-wide n-tile holds all 4
// gates of a j-pair -> gate exchange is 4 shfl.xor(1) within a lane-quad.
// K=100 = 6 x k16 chunks + 1 x k8 chunk (k rows 100..103 zero-padded).
// h stored per-step as f16 hi/lo rows (stride 60 u32, ldmatrix-conflict-free).
// Rec tiles: warp w owns nt = 5w..5w+4. Proj tiles (13): w<3 -> {2w,2w+1},
// else {w+3}. Two CTA barriers per step (read-h2 / write-h2).
// ---------------------------------------------------------------------------
#define THREADS_L 320
#define NT_REC 5
#define BQ_STR 408      // Wh frag array stride (u32), conflict-free
#define WD_STR 104      // Wd frag array stride (u32)
#define H2_STR 60       // h2 row stride (u32)

#define OFF_BHI  0
#define OFF_BLO  21216
#define OFF_WDHI 42432
#define OFF_WDLO 47840
#define OFF_H2HI 53248
#define OFF_H2LO 54208
#define OFF_BD   55168
#define SMEM_L_BYTES (55272 * 4)

__device__ __forceinline__ float sigf(float xv) {
    return __fdividef(1.f, 1.f + __expf(-xv));
}
__device__ __forceinline__ float tanh_f(float xv) {
    float e = __expf(2.f * xv);
    return 1.f - __fdividef(2.f, e + 1.f);
}

__global__ __launch_bounds__(THREADS_L, 1) void lstm_kernel(
    const float* __restrict__ Wh,
    const float* __restrict__ Wd,
    const float* __restrict__ bd,
    float* __restrict__ out)
{
    extern __shared__ uint32_t smL[];
    __half* Bhi_h  = (__half*)(smL + OFF_BHI);
    __half* Blo_h  = (__half*)(smL + OFF_BLO);
    __half* Wdhi_h = (__half*)(smL + OFF_WDHI);
    __half* Wdlo_h = (__half*)(smL + OFF_WDLO);
    __half* h2hi_h = (__half*)(smL + OFF_H2HI);
    __half* h2lo_h = (__half*)(smL + OFF_H2LO);
    float*  sbd    = (float*)(smL + OFF_BD);

    const int tid = threadIdx.x;

    // ---- setup: zero pads, fill fragment arrays ----
    for (int i = tid; i < 2 * BQ_STR; i += THREADS_L) {      // kp 50,51 of Wh
        smL[OFF_BHI + 50 * BQ_STR + i] = 0;
        smL[OFF_BLO + 50 * BQ_STR + i] = 0;
    }
    for (int i = tid; i < 52 * WD_STR; i += THREADS_L) {     // full Wd arrays
        smL[OFF_WDHI + i] = 0;
        smL[OFF_WDLO + i] = 0;
    }
    for (int i = tid; i < 16 * H2_STR; i += THREADS_L) {     // h0 = 0
        smL[OFF_H2HI + i] = 0;
        smL[OFF_H2LO + i] = 0;
    }
    if (tid < 104) sbd[tid] = (tid < HID) ? bd[tid] : 0.f;
    __syncthreads();

    // Wh -> gate-interleaved hi/lo halves: Bf[kp][col'=4j+g], half = k&1
    for (int i = tid; i < HID * G4; i += THREADS_L) {
        int k = i / G4, c = i - k * G4;
        int g = c / HID, j = c - g * HID;
        int colp = 4 * j + g;
        float w = Wh[i];
        __half h = __float2half_rn(w);
        __half l = __float2half_rn((w - __half2float(h)) * 2048.f);
        int hidx = (k >> 1) * (2 * BQ_STR) + colp * 2 + (k & 1);
        Bhi_h[hidx] = h;
        Blo_h[hidx] = l;
    }
    // Wd -> natural columns: Wdf[kp][j], half = k&1
    for (int i = tid; i < HID * HID; i += THREADS_L) {
        int k = i / HID, j = i - k * HID;
        float w = Wd[i];
        __half h = __float2half_rn(w);
        __half l = __float2half_rn((w - __half2float(h)) * 2048.f);
        int hidx = (k >> 1) * (2 * WD_STR) + j * 2 + (k & 1);
        Wdhi_h[hidx] = h;
        Wdlo_h[hidx] = l;
    }
    __syncthreads();

    const int warp = tid >> 5, lane = tid & 31;
    const int gid = lane >> 2, tig = lane & 3;
    const int r0c = blockIdx.x * 16;
    const int ntb = warp * NT_REC;
    const int pstart = (warp < 3) ? 2 * warp : warp + 3;
    const int pcnt   = (warp < 3) ? 2 : 1;

    // ldmatrix lane addresses: row = lane&15, +16B for k-high tiles
    const uint32_t h2hi_b = sptr(h2hi_h) + (lane & 15) * (H2_STR * 4)
                          + (lane >> 4) * 16;
    const uint32_t h2lo_b = sptr(h2lo_h) + (lane & 15) * (H2_STR * 4)
                          + (lane >> 4) * 16;

    // my gate cell per rec tile s: j = 2(ntb+s)+cj, row = crow
    const int cj   = tig >> 1;
    const int crow = gid + (tig & 1) * 8;

    float cst[NT_REC];
#pragma unroll
    for (int s = 0; s < NT_REC; s++) cst[s] = 0.f;

    const float4* xzg = (const float4*)g_xz;
    const float INVL = 1.f / 2048.f;

    for (int t = 0; t < TSTEPS; t++) {
        // xz for this step's cells (consumed late in the step)
        float4 xzc[NT_REC];
#pragma unroll
        for (int s = 0; s < NT_REC; s++) {
            int j = 2 * (ntb + s) + cj;
            xzc[s] = __ldcs(xzg + ((size_t)(r0c + crow) * TSTEPS + t) * HID + j);
        }

        float accH[NT_REC][4], accL[NT_REC][4];
        float pacH[2][4], pacL[2][4];
#pragma unroll
        for (int s = 0; s < NT_REC; s++)
#pragma unroll
            for (int q = 0; q < 4; q++) { accH[s][q] = 0.f; accL[s][q] = 0.f; }
#pragma unroll
        for (int p = 0; p < 2; p++)
#pragma unroll
            for (int q = 0; q < 4; q++) { pacH[p][q] = 0.f; pacL[p][q] = 0.f; }

        // ---- 6 k16 chunks ----
#pragma unroll
        for (int kc = 0; kc < 6; kc++) {
            uint32_t ah0, ah1, ah2, ah3, al0, al1, al2, al3;
            ldmx4(ah0, ah1, ah2, ah3, h2hi_b + kc * 32);
            ldmx4(al0, al1, al2, al3, h2lo_b + kc * 32);

            const uint32_t* Bh0 = smL + OFF_BHI + (kc * 8 + tig) * BQ_STR + gid;
            const uint32_t* Bl0 = smL + OFF_BLO + (kc * 8 + tig) * BQ_STR + gid;
#pragma unroll
            for (int s = 0; s < NT_REC; s++) {
                int off = (ntb + s) * 8;
                uint32_t b0h = Bh0[off], b1h = Bh0[off + 4 * BQ_STR];
                uint32_t b0l = Bl0[off], b1l = Bl0[off + 4 * BQ_STR];
                mma_f16(accH[s], ah0, ah1, ah2, ah3, b0h, b1h);
                mma_f16(accL[s], ah0, ah1, ah2, ah3, b0l, b1l);
                mma_f16(accL[s], al0, al1, al2, al3, b0h, b1h);
            }
            const uint32_t* Wh0 = smL + OFF_WDHI + (kc * 8 + tig) * WD_STR + gid;
            const uint32_t* Wl0 = smL + OFF_WDLO + (kc * 8 + tig) * WD_STR + gid;
#pragma unroll
            for (int p = 0; p < 2; p++) {
                if (p < pcnt) {
                    int off = (pstart + p) * 8;
                    uint32_t b0h = Wh0[off], b1h = Wh0[off + 4 * WD_STR];
                    uint32_t b0l = Wl0[off], b1l = Wl0[off + 4 * WD_STR];
                    mma_f16(pacH[p], ah0, ah1, ah2, ah3, b0h, b1h);
                    mma_f16(pacL[p], ah0, ah1, ah2, ah3, b0l, b1l);
                    mma_f16(pacL[p], al0, al1, al2, al3, b0h, b1h);
                }
            }
        }
        // ---- k8 remainder chunk (k 96..103; 100..103 zero) ----
        {
            uint32_t ah0, ah1, al0, al1;
            ldmx2(ah0, ah1, h2hi_b + 192);
            ldmx2(al0, al1, h2lo_b + 192);
            const uint32_t* Bh = smL + OFF_BHI + (48 + tig) * BQ_STR + gid;
            const uint32_t* Bl = smL + OFF_BLO + (48 + tig) * BQ_STR + gid;
#pragma unroll
            for (int s = 0; s < NT_REC; s++) {
                int off = (ntb + s) * 8;
                uint32_t b0h = Bh[off], b0l = Bl[off];
                mma_f16_k8(accH[s], ah0, ah1, b0h);
                mma_f16_k8(accL[s], ah0, ah1, b0l);
                mma_f16_k8(accL[s], al0, al1, b0h);
            }
            const uint32_t* Wh0 = smL + OFF_WDHI + (48 + tig) * WD_STR + gid;
            const uint32_t* Wl0 = smL + OFF_WDLO + (48 + tig) * WD_STR + gid;
#pragma unroll
            for (int p = 0; p < 2; p++) {
                if (p < pcnt) {
                    int off = (pstart + p) * 8;
                    uint32_t b0h = Wh0[off], b0l = Wl0[off];
                    mma_f16_k8(pacH[p], ah0, ah1, b0h);
                    mma_f16_k8(pacL[p], ah0, ah1, b0l);
                    mma_f16_k8(pacL[p], al0, al1, b0h);
                }
            }
        }

        // ---- projection store (h(t-1) @ Wd -> out[t-1]) ----
        if (t > 0) {
#pragma unroll
            for (int p = 0; p < 2; p++) {
                if (p < pcnt) {
                    int c0 = (pstart + p) * 8 + 2 * tig;
                    if (c0 <= 98) {
                        float b0 = sbd[c0], b1 = sbd[c0 + 1];
                        float v0 = fmaxf(pacH[p][0] + pacL[p][0] * INVL + b0, 0.f);
                        float v1 = fmaxf(pacH[p][1] + pacL[p][1] * INVL + b1, 0.f);
                        float v2 = fmaxf(pacH[p][2] + pacL[p][2] * INVL + b0, 0.f);
                        float v3 = fmaxf(pacH[p][3] + pacL[p][3] * INVL + b1, 0.f);
                        *(float2*)(out + ((size_t)(r0c + gid) * TSTEPS + (t - 1)) * HID + c0)
                            = make_float2(v0, v1);
                        *(float2*)(out + ((size_t)(r0c + gid + 8) * TSTEPS + (t - 1)) * HID + c0)
                            = make_float2(v2, v3);
                    }
                }
            }
        }

        __syncthreads();   // all ldmatrix reads of h2 complete

        // ---- gates: 4 shfls per tile, then per-cell c/h update ----
#pragma unroll
        for (int s = 0; s < NT_REC; s++) {
            float z0 = accH[s][0] + accL[s][0] * INVL;
            float z1 = accH[s][1] + accL[s][1] * INVL;
            float z2 = accH[s][2] + accL[s][2] * INVL;
            float z3 = accH[s][3] + accL[s][3] * INVL;
            float x0 = __shfl_xor_sync(0xffffffffu, z0, 1);
            float x1 = __shfl_xor_sync(0xffffffffu, z1, 1);
            float x2 = __shfl_xor_sync(0xffffffffu, z2, 1);
            float x3 = __shfl_xor_sync(0xffffffffu, z3, 1);
            float zi, zf, zg, zo;
            if ((tig & 1) == 0) { zi = z0; zf = z1; zg = x0; zo = x1; }
            else                { zi = x2; zf = x3; zg = z2; zo = z3; }
            zi += xzc[s].x; zf += xzc[s].y; zg += xzc[s].z; zo += xzc[s].w;
            float ig = sigf(zi), fg = sigf(zf);
            float gg = tanh_f(zg), og = sigf(zo);
            float c = fg * cst[s] + ig * gg;
            cst[s] = c;
            float h = og * tanh_f(c);
            __half hh = __float2half_rn(h);
            __half hl = __float2half_rn((h - __half2float(hh)) * 2048.f);
            int j = 2 * (ntb + s) + cj;
            h2hi_h[crow * (H2_STR * 2) + j] = hh;
            h2lo_h[crow * (H2_STR * 2) + j] = hl;
        }
        __syncthreads();   // h(t) visible for next step
    }

    // ---- epilogue: projection of h(249) -> out[249] ----
    {
        float pacH[2][4], pacL[2][4];
#pragma unroll
        for (int p = 0; p < 2; p++)
#pragma unroll
            for (int q = 0; q < 4; q++) { pacH[p][q] = 0.f; pacL[p][q] = 0.f; }

#pragma unroll
        for (int kc = 0; kc < 6; kc++) {
            uint32_t ah0, ah1, ah2, ah3, al0, al1, al2, al3;
            ldmx4(ah0, ah1, ah2, ah3, h2hi_b + kc * 32);
            ldmx4(al0, al1, al2, al3, h2lo_b + kc * 32);
            const uint32_t* Wh0 = smL + OFF_WDHI + (kc * 8 + tig) * WD_STR + gid;
            const uint32_t* Wl0 = smL + OFF_WDLO + (kc * 8 + tig) * WD_STR + gid;
#pragma unroll
            for (int p = 0; p < 2; p++) {
                if (p < pcnt) {
                    int off = (pstart + p) * 8;
                    uint32_t b0h = Wh0[off], b1h = Wh0[off + 4 * WD_STR];
                    uint32_t b0l = Wl0[off], b1l = Wl0[off + 4 * WD_STR];
                    mma_f16(pacH[p], ah0, ah1, ah2, ah3, b0h, b1h);
                    mma_f16(pacL[p], ah0, ah1, ah2, ah3, b0l, b1l);
                    mma_f16(pacL[p], al0, al1, al2, al3, b0h, b1h);
                }
            }
        }
        {
            uint32_t ah0, ah1, al0, al1;
            ldmx2(ah0, ah1, h2hi_b + 192);
            ldmx2(al0, al1, h2lo_b + 192);
            const uint32_t* Wh0 = smL + OFF_WDHI + (48 + tig) * WD_STR + gid;
            const uint32_t* Wl0 = smL + OFF_WDLO + (48 + tig) * WD_STR + gid;
#pragma unroll
            for (int p = 0; p < 2; p++) {
                if (p < pcnt) {
                    int off = (pstart + p) * 8;
                    uint32_t b0h = Wh0[off], b0l = Wl0[off];
                    mma_f16_k8(pacH[p], ah0, ah1, b0h);
                    mma_f16_k8(pacL[p], ah0, ah1, b0l);
                    mma_f16_k8(pacL[p], al0, al1, b0h);
                }
            }
        }
#pragma unroll
        for (int p = 0; p < 2; p++) {
            if (p < pcnt) {
                int c0 = (pstart + p) * 8 + 2 * tig;
                if (c0 <= 98) {
                    float b0 = sbd[c0], b1 = sbd[c0 + 1];
                    float v0 = fmaxf(pacH[p][0] + pacL[p][0] * INVL + b0, 0.f);
                    float v1 = fmaxf(pacH[p][1] + pacL[p][1] * INVL + b1, 0.f);
                    float v2 = fmaxf(pacH[p][2] + pacL[p][2] * INVL + b0, 0.f);
                    float v3 = fmaxf(pacH[p][3] + pacL[p][3] * INVL + b1, 0.f);
                    *(float2*)(out + ((size_t)(r0c + gid) * TSTEPS + (TSTEPS - 1)) * HID + c0)
                        = make_float2(v0, v1);
                    *(float2*)(out + ((size_t)(r0c + gid + 8) * TSTEPS + (TSTEPS - 1)) * HID + c0)
                        = make_float2(v2, v3);
                }
            }
        }
    }
}

// ---------------------------------------------------------------------------
// Launch
// ---------------------------------------------------------------------------
extern "C" void kernel_launch(void* const* d_in, const int* in_sizes, int n_in,
                              void* d_out, int out_size)
{
    const float* x  = (const float*)d_in[0];   // [2048,250,128]
    const float* Wi = (const float*)d_in[1];   // [128,400]
    const float* Wh = (const float*)d_in[2];   // [100,400]
    const float* bh = (const float*)d_in[3];   // [400]
    const float* Wd = (const float*)d_in[4];   // [100,100]
    const float* bd = (const float*)d_in[5];   // [100]
    float* out = (float*)d_out;                // [2048,250,100]

    const int smem1 = (2 * 64 * A_STR + 2 * 64 * B_STR) * 4 + 80 * 4; // 88,384 B
    cudaFuncSetAttribute(gemm_xz_kernel,
                         cudaFuncAttributeMaxDynamicSharedMemorySize, smem1);
    cudaFuncSetAttribute(lstm_kernel,
                         cudaFuncAttributeMaxDynamicSharedMemorySize, SMEM_L_BYTES);

    wi_split_kernel<<<(64 * G4 + 255) / 256, 256>>>(Wi);
    dim3 g1(MTOT / BM, 5);   // 8000 x 5
    gemm_xz_kernel<<<g1, 128, smem1>>>(x, bh);
    lstm_kernel<<<BATCH / 16, THREADS_L, SMEM_L_BYTES>>>(Wh, Wd, bd, out);
}